// round 9
// baseline (speedup 1.0000x reference)
#include <cuda_runtime.h>
#include <cuda_bf16.h>
#include <cstdint>
#include <math.h>

// Problem constants
#define NTOK 8192
#define NROWS 262144

// Scratch (static __device__ — no allocations allowed)
__device__ __nv_bfloat16 g_Btb[256*256];   // W_h top, transposed [n][k], bf16
__device__ __nv_bfloat16 g_Wfb[256*256];   // (W_ego @ W_h_bot) transposed [j][e], bf16
__device__ float g_fbpart[8*256];          // partial b_ego @ W_h_bot
__device__ float g_ego[NTOK*256];          // ego contribution (fp32)
__device__ float g_logits[NROWS*4];
__device__ int   g_det[8];                 // mask-is-byte partial flags

__device__ __forceinline__ float wsum(float v){
    #pragma unroll
    for (int o = 16; o; o >>= 1) v += __shfl_xor_sync(0xffffffffu, v, o);
    return v;
}
__device__ __forceinline__ float wmax(float v){
    #pragma unroll
    for (int o = 16; o; o >>= 1) v = fmaxf(v, __shfl_xor_sync(0xffffffffu, v, o));
    return v;
}
__device__ __forceinline__ float fast_tanh(float x){
    float y;
    asm("tanh.approx.f32 %0, %1;" : "=f"(y) : "f"(x));
    return y;
}
__device__ __forceinline__ float gelu_tanh(float x){
    float x3 = x * x * x;
    return 0.5f * x * (1.0f + fast_tanh(0.7978845608028654f * fmaf(0.044715f, x3, x)));
}
__device__ __forceinline__ uint32_t pack_bf2(float a, float b){
    __nv_bfloat162 h = __floats2bfloat162_rn(a, b);   // a -> .x (low)
    return *(uint32_t*)&h;
}

#define MMA_BF16(d, a, b0v, b1v) \
    asm("mma.sync.aligned.m16n8k16.row.col.f32.bf16.bf16.f32 " \
        "{%0,%1,%2,%3}, {%4,%5,%6,%7}, {%8,%9}, {%0,%1,%2,%3};" \
        : "+f"(d[0]), "+f"(d[1]), "+f"(d[2]), "+f"(d[3]) \
        : "r"(a[0]), "r"(a[1]), "r"(a[2]), "r"(a[3]), "r"(b0v), "r"(b1v))

#define LDSM_X4(r0, r1, r2, r3, addr) \
    asm volatile("ldmatrix.sync.aligned.m8n8.x4.shared.b16 {%0,%1,%2,%3}, [%4];" \
        : "=r"(r0), "=r"(r1), "=r"(r2), "=r"(r3) : "r"(addr))

// ---------------------------------------------------------------------------
// k_prep: concurrent roles by blockIdx:
//   0..255   : g_Btb column (bf16 transpose of W_h top) + g_Wfb column
//   256..263 : mask width detect -> g_det
//   264..271 : b_ego @ W_h_bot partials -> g_fbpart
// ---------------------------------------------------------------------------
__global__ void __launch_bounds__(256) k_prep(const float* __restrict__ Wh,
                                              const float* __restrict__ We,
                                              const float* __restrict__ be,
                                              const void*  __restrict__ mask){
    int bid = blockIdx.x, tid = threadIdx.x;
    if (bid < 256){
        g_Btb[bid*256 + tid] = __float2bfloat16(Wh[tid*256 + bid]);
        __shared__ float s[256];
        s[tid] = We[bid*256 + tid];
        __syncthreads();
        float a0=0.f, a1=0.f, a2=0.f, a3=0.f;
        const float* Wb = Wh + 256*256 + tid;
        #pragma unroll 8
        for (int t = 0; t < 256; t += 4){
            a0 = fmaf(s[t],   Wb[(t  )*256], a0);
            a1 = fmaf(s[t+1], Wb[(t+1)*256], a1);
            a2 = fmaf(s[t+2], Wb[(t+2)*256], a2);
            a3 = fmaf(s[t+3], Wb[(t+3)*256], a3);
        }
        g_Wfb[tid*256 + bid] = __float2bfloat16((a0+a1) + (a2+a3));  // [j][e]
    } else if (bid < 264){
        int db = bid - 256;
        __shared__ int f;
        if (tid == 0) f = 0;
        __syncthreads();
        const uint4* m4 = (const uint4*)mask;
        unsigned loc = 0;
        #pragma unroll
        for (int q = 0; q < 8; q++){
            uint4 v = m4[db*2048 + q*256 + tid];
            loc |= (v.x | v.y | v.z | v.w) & 0xFFFFFF00u;
        }
        if (loc) atomicOr(&f, 1);
        __syncthreads();
        if (tid == 0) g_det[db] = f;
    } else {
        int db = bid - 264;
        __shared__ float s[32];
        if (tid < 32) s[tid] = be[db*32 + tid];
        __syncthreads();
        float acc = 0.f;
        const float* Wb = Wh + (256 + db*32)*256 + tid;
        #pragma unroll
        for (int t = 0; t < 32; t++)
            acc = fmaf(s[t], Wb[t*256], acc);
        g_fbpart[db*256 + tid] = acc;
    }
}

// Shared geometry: resident B [n256][k256] bf16, row stride 264 elems.
// LDSM bank check: row start bank = (264*2*r/4)%32 = (132r)%32 = 4r%32 ->
// 8-row phase covers banks {4r..4r+3 | r=0..7} = all 32, conflict-free.
#define BST 264
#define B_BYTES (256*BST*2)          // 135168
#define ASTB 264

// ---------------------------------------------------------------------------
// k_egomma: g_ego = ego_ctx @ Wf + biasc.
// M=64 tiles, grid=128, 512 threads (16 warps: 2m x 8n, warp m32n32).
// Resident B, barrier-free mainloop.
// ---------------------------------------------------------------------------
#define EGO_AS_BYTES (64*ASTB*2)     // 33792
#define EGO_SMEM (EGO_AS_BYTES + B_BYTES + 1024)
__global__ void __launch_bounds__(512, 1) k_egomma(const float* __restrict__ ego,
                                                   const float* __restrict__ bh){
    extern __shared__ char smraw[];
    __nv_bfloat16* As = (__nv_bfloat16*)smraw;
    __nv_bfloat16* Bs = (__nv_bfloat16*)(smraw + EGO_AS_BYTES);
    float* bias_sm    = (float*)(smraw + EGO_AS_BYTES + B_BYTES);

    int tid = threadIdx.x, lane = tid & 31, wid = tid >> 5;
    int g = lane >> 2, tg = lane & 3;
    int wm = wid >> 3, wn = wid & 7;
    size_t rowbase = (size_t)blockIdx.x * 64;

    if (tid < 256){
        float b = bh[tid];
        #pragma unroll
        for (int q = 0; q < 8; q++) b += g_fbpart[q*256 + tid];
        bias_sm[tid] = b;
    }

    // Resident B load: 512 threads, row = tid>>1, half = tid&1, 16 uint4 each
    {
        const uint4* Bg = (const uint4*)g_Wfb;
        int row = tid >> 1, half = tid & 1;
        #pragma unroll
        for (int q = 0; q < 16; q++){
            uint4 v = Bg[row*32 + half*16 + q];
            *(uint4*)(Bs + row*BST + half*128 + q*8) = v;
        }
    }

    // A convert: warp handles rows wid*4..+3
    #pragma unroll
    for (int rr = 0; rr < 4; rr++){
        int row = wid*4 + rr;
        const float4* src = (const float4*)(ego + (rowbase + row)*256);
        float4 v0 = src[lane*2], v1 = src[lane*2 + 1];
        uint4 pk;
        pk.x = pack_bf2(v0.x, v0.y);
        pk.y = pack_bf2(v0.z, v0.w);
        pk.z = pack_bf2(v1.x, v1.y);
        pk.w = pack_bf2(v1.z, v1.w);
        *(uint4*)(As + row*ASTB + lane*8) = pk;
    }
    __syncthreads();

    float acc[2][4][4];
    #pragma unroll
    for (int mt = 0; mt < 2; mt++)
        #pragma unroll
        for (int nt = 0; nt < 4; nt++)
            #pragma unroll
            for (int e = 0; e < 4; e++) acc[mt][nt][e] = 0.f;

    uint32_t As_u32 = (uint32_t)__cvta_generic_to_shared(As);
    uint32_t Bs_u32 = (uint32_t)__cvta_generic_to_shared(Bs);
    uint32_t aAddr = As_u32 + ((wm*32 + (lane & 15))*ASTB + ((lane >> 4) << 3)) * 2;
    uint32_t bAddr = Bs_u32 + ((wn*32 + ((lane >> 1) & 8) + (lane & 7))*BST
                               + (lane & 8)) * 2;

    #pragma unroll
    for (int ch = 0; ch < 16; ch++){
        uint32_t a[2][4], b[2][4];
        LDSM_X4(a[0][0], a[0][1], a[0][2], a[0][3], aAddr + ch*32);
        LDSM_X4(a[1][0], a[1][1], a[1][2], a[1][3], aAddr + ch*32 + 16*ASTB*2);
        LDSM_X4(b[0][0], b[0][1], b[0][2], b[0][3], bAddr + ch*32);
        LDSM_X4(b[1][0], b[1][1], b[1][2], b[1][3], bAddr + ch*32 + 16*BST*2);
        #pragma unroll
        for (int nt = 0; nt < 4; nt++)
            #pragma unroll
            for (int mt = 0; mt < 2; mt++)
                MMA_BF16(acc[mt][nt], a[mt], b[nt>>1][2*(nt&1)], b[nt>>1][2*(nt&1)+1]);
    }

    #pragma unroll
    for (int mt = 0; mt < 2; mt++)
        #pragma unroll
        for (int nt = 0; nt < 4; nt++){
            int c = wn*32 + nt*8 + 2*tg;
            float bx = bias_sm[c], by = bias_sm[c+1];
            #pragma unroll
            for (int hi = 0; hi < 2; hi++){
                int rrow = wm*32 + mt*16 + g + 8*hi;
                float2 v = make_float2(acc[mt][nt][hi*2] + bx,
                                       acc[mt][nt][hi*2+1] + by);
                *(float2*)&g_ego[(rowbase + rrow)*256 + c] = v;
            }
        }
}

__global__ void k_nop(){}

// ---------------------------------------------------------------------------
// k_main: 1024 threads, 32 warps (4M x 8N), warp tile m32 x n32.
// Resident B (full 256x256 bf16 in smem), barrier-free unrolled mainloop
// (one __syncthreads total). Fragment-space epilogue.
// ---------------------------------------------------------------------------
#define AS_BYTES (128*ASTB*2)        // 67584
#define MAIN_SMEM (AS_BYTES + B_BYTES + 4096 + 2048)   // 208896
__global__ void __launch_bounds__(1024, 1) k_main(const float* __restrict__ inv,
                                                  const float* __restrict__ lns,
                                                  const float* __restrict__ lnb,
                                                  const float* __restrict__ Wl){
    extern __shared__ char smraw[];
    __nv_bfloat16* As = (__nv_bfloat16*)smraw;
    __nv_bfloat16* Bs = (__nv_bfloat16*)(smraw + AS_BYTES);
    float* Wls        = (float*)(smraw + AS_BYTES + B_BYTES);           // 1024 f
    float* Lsm        = (float*)(smraw + AS_BYTES + B_BYTES + 4096);    // 512 f

    int tid = threadIdx.x, lane = tid & 31, wid = tid >> 5;
    int g = lane >> 2, tg = lane & 3;
    int wm = wid >> 3, wn = wid & 7;
    size_t rowbase = (size_t)blockIdx.x * 128;

    Wls[tid] = Wl[tid];
    if (tid < 512) Lsm[tid] = 0.f;

    // Resident B load: 1024 threads, row = tid>>2, quarter = tid&3, 8 uint4
    {
        const uint4* Bg = (const uint4*)g_Btb;
        int row = tid >> 2, qt = tid & 3;
        #pragma unroll
        for (int q = 0; q < 8; q++){
            uint4 v = Bg[row*32 + qt*8 + q];
            *(uint4*)(Bs + row*BST + qt*64 + q*8) = v;
        }
    }

    // LN scale/bias for this lane's 8-element slice
    const float4* lns4 = (const float4*)lns;
    const float4* lnb4 = (const float4*)lnb;
    float4 sc0 = lns4[lane*2], sc1 = lns4[lane*2 + 1];
    float4 sb0 = lnb4[lane*2], sb1 = lnb4[lane*2 + 1];

    // LN pre-pass: warp handles rows wid*4..+3
    #pragma unroll
    for (int rr = 0; rr < 4; rr++){
        int row = wid*4 + rr;
        const float4* src = (const float4*)(inv + (rowbase + row)*256);
        float4 v0 = src[lane*2], v1 = src[lane*2 + 1];
        float s = v0.x+v0.y+v0.z+v0.w + v1.x+v1.y+v1.z+v1.w;
        float q = v0.x*v0.x+v0.y*v0.y+v0.z*v0.z+v0.w*v0.w
                + v1.x*v1.x+v1.y*v1.y+v1.z*v1.z+v1.w*v1.w;
        s = wsum(s); q = wsum(q);
        float mean = s * (1.f/256.f);
        float var  = q * (1.f/256.f) - mean*mean;
        float rstd = rsqrtf(var + 1e-6f);
        uint4 pk;
        pk.x = pack_bf2((v0.x-mean)*rstd*sc0.x + sb0.x, (v0.y-mean)*rstd*sc0.y + sb0.y);
        pk.y = pack_bf2((v0.z-mean)*rstd*sc0.z + sb0.z, (v0.w-mean)*rstd*sc0.w + sb0.w);
        pk.z = pack_bf2((v1.x-mean)*rstd*sc1.x + sb1.x, (v1.y-mean)*rstd*sc1.y + sb1.y);
        pk.w = pack_bf2((v1.z-mean)*rstd*sc1.z + sb1.z, (v1.w-mean)*rstd*sc1.w + sb1.w);
        *(uint4*)(As + row*ASTB + lane*8) = pk;
    }
    __syncthreads();   // the only block-wide barrier before the epilogue

    float acc[2][4][4];
    #pragma unroll
    for (int mt = 0; mt < 2; mt++)
        #pragma unroll
        for (int nt = 0; nt < 4; nt++)
            #pragma unroll
            for (int e = 0; e < 4; e++) acc[mt][nt][e] = 0.f;

    uint32_t As_u32 = (uint32_t)__cvta_generic_to_shared(As);
    uint32_t Bs_u32 = (uint32_t)__cvta_generic_to_shared(Bs);
    uint32_t aAddr = As_u32 + ((wm*32 + (lane & 15))*ASTB + ((lane >> 4) << 3)) * 2;
    uint32_t bAddr = Bs_u32 + ((wn*32 + ((lane >> 1) & 8) + (lane & 7))*BST
                               + (lane & 8)) * 2;

    #pragma unroll
    for (int ch = 0; ch < 16; ch++){
        uint32_t a[2][4], b[2][4];
        LDSM_X4(a[0][0], a[0][1], a[0][2], a[0][3], aAddr + ch*32);
        LDSM_X4(a[1][0], a[1][1], a[1][2], a[1][3], aAddr + ch*32 + 16*ASTB*2);
        LDSM_X4(b[0][0], b[0][1], b[0][2], b[0][3], bAddr + ch*32);
        LDSM_X4(b[1][0], b[1][1], b[1][2], b[1][3], bAddr + ch*32 + 16*BST*2);
        #pragma unroll
        for (int nt = 0; nt < 4; nt++)
            #pragma unroll
            for (int mt = 0; mt < 2; mt++)
                MMA_BF16(acc[mt][nt], a[mt], b[nt>>1][2*(nt&1)], b[nt>>1][2*(nt&1)+1]);
    }

    // Fragment-space epilogue: warp wm owns token blockIdx*4 + wm
    size_t token = (size_t)blockIdx.x*4 + wm;
    const float* egorow = g_ego + token*256;

    float pl[4][4];
    #pragma unroll
    for (int i = 0; i < 4; i++)
        #pragma unroll
        for (int h = 0; h < 4; h++) pl[i][h] = 0.f;

    #pragma unroll
    for (int nt = 0; nt < 4; nt++){
        int c = wn*32 + nt*8 + 2*tg;
        float2 eg = *(const float2*)(egorow + c);
        float4 w0 = *(const float4*)(Wls + c*4);
        float4 w1 = *(const float4*)(Wls + (c+1)*4);
        #pragma unroll
        for (int mt = 0; mt < 2; mt++)
            #pragma unroll
            for (int hi = 0; hi < 2; hi++){
                float gl0 = gelu_tanh(acc[mt][nt][hi*2]   + eg.x);
                float gl1 = gelu_tanh(acc[mt][nt][hi*2+1] + eg.y);
                int ri = mt*2 + hi;
                pl[ri][0] = fmaf(gl0, w0.x, fmaf(gl1, w1.x, pl[ri][0]));
                pl[ri][1] = fmaf(gl0, w0.y, fmaf(gl1, w1.y, pl[ri][1]));
                pl[ri][2] = fmaf(gl0, w0.z, fmaf(gl1, w1.z, pl[ri][2]));
                pl[ri][3] = fmaf(gl0, w0.w, fmaf(gl1, w1.w, pl[ri][3]));
            }
    }
    // reduce over the 4 lanes of each quad
    #pragma unroll
    for (int o = 1; o <= 2; o <<= 1)
        #pragma unroll
        for (int ri = 0; ri < 4; ri++)
            #pragma unroll
            for (int h = 0; h < 4; h++)
                pl[ri][h] += __shfl_xor_sync(0xffffffffu, pl[ri][h], o);

    if (tg == 0){
        #pragma unroll
        for (int mt = 0; mt < 2; mt++)
            #pragma unroll
            for (int hi = 0; hi < 2; hi++){
                int rrow = wm*32 + mt*16 + g + 8*hi;
                #pragma unroll
                for (int h = 0; h < 4; h++)
                    atomicAdd(&Lsm[rrow*4 + h], pl[mt*2+hi][h]);
            }
    }
    __syncthreads();
    if (tid < 512)
        g_logits[(rowbase + (tid >> 2))*4 + (tid & 3)] = Lsm[tid];
}

// ---------------------------------------------------------------------------
// Masked softmax over K per head + alpha-weighted r/u reductions.
// ---------------------------------------------------------------------------
__global__ void __launch_bounds__(256) k_final(const float* __restrict__ r,
                                               const float* __restrict__ u,
                                               const void* __restrict__ mask,
                                               float* __restrict__ out){
    __shared__ int s_mb;
    int tid = threadIdx.x, lane = tid & 31, w = tid >> 5;
    if (tid == 0){
        int mb = 0;
        #pragma unroll
        for (int q = 0; q < 8; q++) mb |= g_det[q];
        s_mb = mb;
    }
    __syncthreads();
    int T = blockIdx.x * 8 + w;
    size_t row = (size_t)T * 32 + lane;

    float4 l4 = ((const float4*)g_logits)[row];
    float l[4] = {l4.x, l4.y, l4.z, l4.w};

    bool m;
    if (s_mb) m = ((const unsigned char*)mask)[row] != 0;
    else      m = ((const unsigned int*)mask)[row] != 0u;

    float a[4];
    #pragma unroll
    for (int h = 0; h < 4; h++){
        float v = m ? l[h] : -3.402823466e38f;
        float mx = wmax(v);
        float e  = m ? __expf(l[h] - mx) : 0.f;
        float s  = wsum(e);
        a[h] = (s > 0.f) ? (e / s) : 0.f;
    }

    float* alpha_out = out + 2 * (NTOK * 12);
    ((float4*)alpha_out)[row] = make_float4(a[0], a[1], a[2], a[3]);

    float rr[3], uu[3];
    #pragma unroll
    for (int d = 0; d < 3; d++){
        rr[d] = r[row*3 + d];
        uu[d] = u[row*3 + d];
    }

    float orv = 0.f, ouv = 0.f;
    #pragma unroll
    for (int p = 0; p < 12; p++){
        float v1 = a[p/3] * rr[p%3];
        float v2 = a[p/3] * uu[p%3];
        #pragma unroll
        for (int o = 16; o; o >>= 1){
            v1 += __shfl_xor_sync(0xffffffffu, v1, o);
            v2 += __shfl_xor_sync(0xffffffffu, v2, o);
        }
        if (lane == p) orv = v1;
        if (lane == p) ouv = v2;
    }
    if (lane < 12){
        out[(size_t)T*12 + lane]           = orv;   // v_r
        out[NTOK*12 + (size_t)T*12 + lane] = ouv;   // v_u
    }
}

// ---------------------------------------------------------------------------
extern "C" void kernel_launch(void* const* d_in, const int* in_sizes, int n_in,
                              void* d_out, int out_size){
    (void)in_sizes; (void)n_in; (void)out_size;
    const float* inv  = (const float*)d_in[0];   // inv_tok (B,N,K,D)
    const float* ego  = (const float*)d_in[1];   // ego_ctx (B,N,256)
    const float* r    = (const float*)d_in[2];   // (B,N,K,3)
    const float* u    = (const float*)d_in[3];   // (B,N,K,3)
    const void*  mask = d_in[4];                 // (B,N,K) bool/int
    const float* We   = (const float*)d_in[5];   // W_ego (256,256)
    const float* be   = (const float*)d_in[6];   // b_ego (256)
    const float* lns  = (const float*)d_in[7];   // ln_scale (256)
    const float* lnb  = (const float*)d_in[8];   // ln_bias (256)
    const float* Wh   = (const float*)d_in[9];   // W_h (512,256)
    const float* bh   = (const float*)d_in[10];  // b_h (256)
    const float* Wl   = (const float*)d_in[11];  // W_logit (256,4)
    // d_in[12] = b_logit: softmax-invariant, unused.

    cudaFuncSetAttribute(k_main,   cudaFuncAttributeMaxDynamicSharedMemorySize, MAIN_SMEM);
    cudaFuncSetAttribute(k_egomma, cudaFuncAttributeMaxDynamicSharedMemorySize, EGO_SMEM);

    k_prep<<<272, 256>>>(Wh, We, be, mask);
    k_egomma<<<NTOK/64, 512, EGO_SMEM>>>(ego, bh);
    k_nop<<<1, 32>>>();
    k_main<<<2048, 1024, MAIN_SMEM>>>(inv, lns, lnb, Wl);
    k_final<<<NTOK/8, 256>>>(r, u, mask, (float*)d_out);
}

// round 10
// speedup vs baseline: 1.2767x; 1.2767x over previous
#include <cuda_runtime.h>
#include <cuda_bf16.h>
#include <cstdint>
#include <math.h>

// Problem constants
#define NTOK 8192
#define NROWS 262144

// Scratch (static __device__ — no allocations allowed)
__device__ __nv_bfloat16 g_Btb[256*256];   // W_h top, transposed [n][k], bf16
__device__ __nv_bfloat16 g_Wfb[256*256];   // (W_ego @ W_h_bot) transposed [j][e], bf16
__device__ float g_fbpart[8*256];          // partial b_ego @ W_h_bot
__device__ float g_ego[NTOK*256];          // ego contribution (fp32)
__device__ int   g_det[8];                 // mask-is-byte partial flags

__device__ __forceinline__ float wsum(float v){
    #pragma unroll
    for (int o = 16; o; o >>= 1) v += __shfl_xor_sync(0xffffffffu, v, o);
    return v;
}
__device__ __forceinline__ float wmax(float v){
    #pragma unroll
    for (int o = 16; o; o >>= 1) v = fmaxf(v, __shfl_xor_sync(0xffffffffu, v, o));
    return v;
}
__device__ __forceinline__ float fast_tanh(float x){
    float y;
    asm("tanh.approx.f32 %0, %1;" : "=f"(y) : "f"(x));
    return y;
}
__device__ __forceinline__ float gelu_tanh(float x){
    float x3 = x * x * x;
    return 0.5f * x * (1.0f + fast_tanh(0.7978845608028654f * fmaf(0.044715f, x3, x)));
}
__device__ __forceinline__ uint32_t pack_bf2(float a, float b){
    __nv_bfloat162 h = __floats2bfloat162_rn(a, b);   // a -> .x (low)
    return *(uint32_t*)&h;
}

#define MMA_BF16(d, a, b0v, b1v) \
    asm("mma.sync.aligned.m16n8k16.row.col.f32.bf16.bf16.f32 " \
        "{%0,%1,%2,%3}, {%4,%5,%6,%7}, {%8,%9}, {%0,%1,%2,%3};" \
        : "+f"(d[0]), "+f"(d[1]), "+f"(d[2]), "+f"(d[3]) \
        : "r"(a[0]), "r"(a[1]), "r"(a[2]), "r"(a[3]), "r"(b0v), "r"(b1v))

#define LDSM_X4(r0, r1, r2, r3, addr) \
    asm volatile("ldmatrix.sync.aligned.m8n8.x4.shared.b16 {%0,%1,%2,%3}, [%4];" \
        : "=r"(r0), "=r"(r1), "=r"(r2), "=r"(r3) : "r"(addr))

#define CP_ASYNC16(dst, src) \
    asm volatile("cp.async.cg.shared.global [%0], [%1], 16;" \
        :: "r"(dst), "l"(src) : "memory")
#define CP_COMMIT() asm volatile("cp.async.commit_group;" ::: "memory")
#define CP_WAIT1()  asm volatile("cp.async.wait_group 1;" ::: "memory")
#define CP_WAIT0()  asm volatile("cp.async.wait_group 0;" ::: "memory")

// ---------------------------------------------------------------------------
// k_prep: concurrent roles by blockIdx:
//   0..255   : g_Btb column (bf16 transpose of W_h top) + g_Wfb column
//   256..263 : mask width detect -> g_det
//   264..271 : b_ego @ W_h_bot partials -> g_fbpart
// ---------------------------------------------------------------------------
__global__ void __launch_bounds__(256) k_prep(const float* __restrict__ Wh,
                                              const float* __restrict__ We,
                                              const float* __restrict__ be,
                                              const void*  __restrict__ mask){
    int bid = blockIdx.x, tid = threadIdx.x;
    if (bid < 256){
        g_Btb[bid*256 + tid] = __float2bfloat16(Wh[tid*256 + bid]);
        __shared__ float s[256];
        s[tid] = We[bid*256 + tid];
        __syncthreads();
        float a0=0.f, a1=0.f, a2=0.f, a3=0.f;
        const float* Wb = Wh + 256*256 + tid;
        #pragma unroll 8
        for (int t = 0; t < 256; t += 4){
            a0 = fmaf(s[t],   Wb[(t  )*256], a0);
            a1 = fmaf(s[t+1], Wb[(t+1)*256], a1);
            a2 = fmaf(s[t+2], Wb[(t+2)*256], a2);
            a3 = fmaf(s[t+3], Wb[(t+3)*256], a3);
        }
        g_Wfb[tid*256 + bid] = __float2bfloat16((a0+a1) + (a2+a3));  // [j][e]
    } else if (bid < 264){
        int db = bid - 256;
        __shared__ int f;
        if (tid == 0) f = 0;
        __syncthreads();
        const uint4* m4 = (const uint4*)mask;
        unsigned loc = 0;
        #pragma unroll
        for (int q = 0; q < 8; q++){
            uint4 v = m4[db*2048 + q*256 + tid];
            loc |= (v.x | v.y | v.z | v.w) & 0xFFFFFF00u;
        }
        if (loc) atomicOr(&f, 1);
        __syncthreads();
        if (tid == 0) g_det[db] = f;
    } else {
        int db = bid - 264;
        __shared__ float s[32];
        if (tid < 32) s[tid] = be[db*32 + tid];
        __syncthreads();
        float acc = 0.f;
        const float* Wb = Wh + (256 + db*32)*256 + tid;
        #pragma unroll
        for (int t = 0; t < 32; t++)
            acc = fmaf(s[t], Wb[t*256], acc);
        g_fbpart[db*256 + tid] = acc;
    }
}

// Shared geometry
#define ASTB 264
#define BSTB 24
#define AS_BYTES (128*ASTB*2)        // 67584
#define BCH_ELEM (256*BSTB)          // elems per k16 chunk buffer (6144)
#define BCH_BYTES (BCH_ELEM*2)       // 12288

// ---------------------------------------------------------------------------
// k_egomma: g_ego = ego_ctx @ Wf + biasc (R6 version, known good)
// ---------------------------------------------------------------------------
#define EGO_BS_HALF (256*BSTB)
#define EGO_SMEM (AS_BYTES + 2*EGO_BS_HALF*2 + 1024)
__global__ void __launch_bounds__(512, 1) k_egomma(const float* __restrict__ ego,
                                                   const float* __restrict__ bh){
    extern __shared__ char smraw[];
    __nv_bfloat16* As = (__nv_bfloat16*)smraw;
    __nv_bfloat16* Bs = (__nv_bfloat16*)(smraw + AS_BYTES);
    float* bias_sm    = (float*)(smraw + AS_BYTES + 2*EGO_BS_HALF*2);

    int tid = threadIdx.x, lane = tid & 31, wid = tid >> 5;
    int g = lane >> 2, tg = lane & 3;
    int wm = wid >> 2, wn = wid & 3;
    size_t rowbase = (size_t)blockIdx.x * 128;

    if (tid < 256){
        float b = bh[tid];
        #pragma unroll
        for (int q = 0; q < 8; q++) b += g_fbpart[q*256 + tid];
        bias_sm[tid] = b;
    }

    for (int rr = 0; rr < 8; rr++){
        int row = wid*8 + rr;
        const float4* src = (const float4*)(ego + (rowbase + row)*256);
        float4 v0 = src[lane*2], v1 = src[lane*2 + 1];
        uint4 pk;
        pk.x = pack_bf2(v0.x, v0.y);
        pk.y = pack_bf2(v0.z, v0.w);
        pk.z = pack_bf2(v1.x, v1.y);
        pk.w = pack_bf2(v1.z, v1.w);
        *(uint4*)(As + row*ASTB + lane*8) = pk;
    }

    float acc[2][8][4];
    #pragma unroll
    for (int mt = 0; mt < 2; mt++)
        #pragma unroll
        for (int nt = 0; nt < 8; nt++)
            #pragma unroll
            for (int e = 0; e < 4; e++) acc[mt][nt][e] = 0.f;

    int bn = tid & 255, bkh = tid >> 8;
    const uint4* Bg = (const uint4*)g_Wfb;
    uint4 pf = Bg[bn*32 + bkh];
    *(uint4*)(Bs + bn*BSTB + bkh*8) = pf;

    for (int ch = 0; ch < 16; ch++){
        __syncthreads();
        if (ch + 1 < 16) pf = Bg[bn*32 + (ch+1)*2 + bkh];
        const __nv_bfloat16* Bc = Bs + (ch & 1)*EGO_BS_HALF;

        uint32_t a[2][4];
        #pragma unroll
        for (int mt = 0; mt < 2; mt++){
            const __nv_bfloat16* Ar = As + (wm*32 + mt*16 + g)*ASTB + ch*16;
            a[mt][0] = *(const uint32_t*)(Ar + 2*tg);
            a[mt][1] = *(const uint32_t*)(Ar + 8*ASTB + 2*tg);
            a[mt][2] = *(const uint32_t*)(Ar + 2*tg + 8);
            a[mt][3] = *(const uint32_t*)(Ar + 8*ASTB + 2*tg + 8);
        }
        #pragma unroll
        for (int nt = 0; nt < 8; nt++){
            const __nv_bfloat16* Br = Bc + (wn*64 + nt*8 + g)*BSTB + 2*tg;
            uint32_t b0 = *(const uint32_t*)(Br);
            uint32_t b1 = *(const uint32_t*)(Br + 8);
            #pragma unroll
            for (int mt = 0; mt < 2; mt++)
                MMA_BF16(acc[mt][nt], a[mt], b0, b1);
        }
        if (ch + 1 < 16){
            __nv_bfloat16* Bn = Bs + ((ch+1) & 1)*EGO_BS_HALF;
            *(uint4*)(Bn + bn*BSTB + bkh*8) = pf;
        }
    }

    #pragma unroll
    for (int mt = 0; mt < 2; mt++)
        #pragma unroll
        for (int nt = 0; nt < 8; nt++){
            int c = wn*64 + nt*8 + 2*tg;
            float bx = bias_sm[c], by = bias_sm[c+1];
            #pragma unroll
            for (int hi = 0; hi < 2; hi++){
                int rrow = wm*32 + mt*16 + g + 8*hi;
                float2 v = make_float2(acc[mt][nt][hi*2] + bx,
                                       acc[mt][nt][hi*2+1] + by);
                *(float2*)&g_ego[(rowbase + rrow)*256 + c] = v;
            }
        }
}

__global__ void k_nop(){}

// ---------------------------------------------------------------------------
// k_main: 1024 threads, 32 warps (4M x 8N), warp tile m32 x n32 (R6 geometry).
// B staged via cp.async: k32 stages, 3 buffers, issued 2 stages ahead
// (stages 0,1 issued before LN so latency hides under LN). 8 stage barriers.
// Fragment-space epilogue + FUSED softmax/readout tail (block owns 4 tokens).
// SMEM: As 67584 | Bst 3*24576 | Wls 4096 | Lsm 2048 | flag 64
// ---------------------------------------------------------------------------
#define BST_BYTES (2*BCH_BYTES)          // one k32 stage = 24576
#define SM_BS   AS_BYTES
#define SM_WL   (AS_BYTES + 3*BST_BYTES)             // 141312
#define SM_LS   (SM_WL + 4096)                        // 145408
#define SM_FLAG (SM_LS + 2048)                        // 147456
#define MAIN_SMEM (SM_FLAG + 64)                      // 147520

__global__ void __launch_bounds__(1024, 1) k_main(const float* __restrict__ inv,
                                                  const float* __restrict__ lns,
                                                  const float* __restrict__ lnb,
                                                  const float* __restrict__ Wl,
                                                  const float* __restrict__ r,
                                                  const float* __restrict__ u,
                                                  const void*  __restrict__ mask,
                                                  float* __restrict__ out){
    extern __shared__ char smraw[];
    __nv_bfloat16* As = (__nv_bfloat16*)smraw;
    float* Wls = (float*)(smraw + SM_WL);
    float* Lsm = (float*)(smraw + SM_LS);
    int*   Flg = (int*)(smraw + SM_FLAG);

    int tid = threadIdx.x, lane = tid & 31, wid = tid >> 5;
    int g = lane >> 2, tg = lane & 3;
    int wm = wid >> 3, wn = wid & 7;
    size_t rowbase = (size_t)blockIdx.x * 128;

    uint32_t smb = (uint32_t)__cvta_generic_to_shared(smraw);
    uint32_t Bs_base = smb + SM_BS;

    // B stage issue: thread -> (chunk c, n, half); 16B per thread per stage
    const uint4* Bg = (const uint4*)g_Btb;     // [n][k]: 32 uint4 per n
    int sc = tid >> 9, snn = (tid >> 1) & 255, shf = tid & 1;
    uint32_t st_dst_off = (uint32_t)(sc*BCH_ELEM + snn*BSTB + shf*8) * 2;
    const uint4* st_src0 = Bg + snn*32 + sc*2 + shf;

    // issue stages 0 and 1 (overlap with LN below)
    CP_ASYNC16(Bs_base + 0*BST_BYTES + st_dst_off, (const void*)(st_src0 + 0*4));
    CP_COMMIT();
    CP_ASYNC16(Bs_base + 1*BST_BYTES + st_dst_off, (const void*)(st_src0 + 1*4));
    CP_COMMIT();

    Wls[tid] = Wl[tid];
    if (tid < 512) Lsm[tid] = 0.f;
    if (tid == 0){
        int mb = 0;
        #pragma unroll
        for (int q = 0; q < 8; q++) mb |= g_det[q];
        Flg[0] = mb;
    }

    // LN scale/bias for this lane's 8-element slice
    const float4* lns4 = (const float4*)lns;
    const float4* lnb4 = (const float4*)lnb;
    float4 sc0 = lns4[lane*2], sc1 = lns4[lane*2 + 1];
    float4 sb0 = lnb4[lane*2], sb1 = lnb4[lane*2 + 1];

    // LN pre-pass: warp handles rows wid*4..+3
    #pragma unroll
    for (int rr = 0; rr < 4; rr++){
        int row = wid*4 + rr;
        const float4* src = (const float4*)(inv + (rowbase + row)*256);
        float4 v0 = src[lane*2], v1 = src[lane*2 + 1];
        float s = v0.x+v0.y+v0.z+v0.w + v1.x+v1.y+v1.z+v1.w;
        float q = v0.x*v0.x+v0.y*v0.y+v0.z*v0.z+v0.w*v0.w
                + v1.x*v1.x+v1.y*v1.y+v1.z*v1.z+v1.w*v1.w;
        s = wsum(s); q = wsum(q);
        float mean = s * (1.f/256.f);
        float var  = q * (1.f/256.f) - mean*mean;
        float rstd = rsqrtf(var + 1e-6f);
        uint4 pk;
        pk.x = pack_bf2((v0.x-mean)*rstd*sc0.x + sb0.x, (v0.y-mean)*rstd*sc0.y + sb0.y);
        pk.y = pack_bf2((v0.z-mean)*rstd*sc0.z + sb0.z, (v0.w-mean)*rstd*sc0.w + sb0.w);
        pk.z = pack_bf2((v1.x-mean)*rstd*sc1.x + sb1.x, (v1.y-mean)*rstd*sc1.y + sb1.y);
        pk.w = pack_bf2((v1.z-mean)*rstd*sc1.z + sb1.z, (v1.w-mean)*rstd*sc1.w + sb1.w);
        *(uint4*)(As + row*ASTB + lane*8) = pk;
    }

    float acc[2][4][4];
    #pragma unroll
    for (int mt = 0; mt < 2; mt++)
        #pragma unroll
        for (int nt = 0; nt < 4; nt++)
            #pragma unroll
            for (int e = 0; e < 4; e++) acc[mt][nt][e] = 0.f;

    uint32_t aAddr = smb + ((wm*32 + (lane & 15))*ASTB + ((lane >> 4) << 3)) * 2;
    uint32_t bAddr = Bs_base + (((wn*32 + ((lane >> 1) & 8) + (lane & 7))*BSTB
                                + (lane & 8))) * 2;

    #pragma unroll
    for (int s = 0; s < 8; s++){
        if (s < 7) { CP_WAIT1(); } else { CP_WAIT0(); }
        __syncthreads();    // stage s data visible to all; stage s-1 compute done
        if (s + 2 < 8){
            CP_ASYNC16(Bs_base + ((s+2)%3)*BST_BYTES + st_dst_off,
                       (const void*)(st_src0 + (s+2)*4));
            CP_COMMIT();
        }
        uint32_t bufB = bAddr + (s%3)*BST_BYTES;

        #pragma unroll
        for (int sub = 0; sub < 2; sub++){
            int ch = s*2 + sub;
            uint32_t a[2][4];
            LDSM_X4(a[0][0], a[0][1], a[0][2], a[0][3], aAddr + ch*32);
            LDSM_X4(a[1][0], a[1][1], a[1][2], a[1][3], aAddr + ch*32 + 16*ASTB*2);
            #pragma unroll
            for (int p = 0; p < 2; p++){
                uint32_t b[4];
                LDSM_X4(b[0], b[1], b[2], b[3],
                        bufB + sub*BCH_BYTES + p*16*BSTB*2);
                #pragma unroll
                for (int q = 0; q < 2; q++){
                    int nt = p*2 + q;
                    #pragma unroll
                    for (int mt = 0; mt < 2; mt++)
                        MMA_BF16(acc[mt][nt], a[mt], b[2*q], b[2*q+1]);
                }
            }
        }
    }

    // Fragment-space epilogue: warp wm owns token blockIdx*4 + wm
    size_t token = (size_t)blockIdx.x*4 + wm;
    const float* egorow = g_ego + token*256;

    float pl[4][4];
    #pragma unroll
    for (int i = 0; i < 4; i++)
        #pragma unroll
        for (int h = 0; h < 4; h++) pl[i][h] = 0.f;

    #pragma unroll
    for (int nt = 0; nt < 4; nt++){
        int c = wn*32 + nt*8 + 2*tg;
        float2 eg = *(const float2*)(egorow + c);
        float4 w0 = *(const float4*)(Wls + c*4);
        float4 w1 = *(const float4*)(Wls + (c+1)*4);
        #pragma unroll
        for (int mt = 0; mt < 2; mt++)
            #pragma unroll
            for (int hi = 0; hi < 2; hi++){
                float gl0 = gelu_tanh(acc[mt][nt][hi*2]   + eg.x);
                float gl1 = gelu_tanh(acc[mt][nt][hi*2+1] + eg.y);
                int ri = mt*2 + hi;
                pl[ri][0] = fmaf(gl0, w0.x, fmaf(gl1, w1.x, pl[ri][0]));
                pl[ri][1] = fmaf(gl0, w0.y, fmaf(gl1, w1.y, pl[ri][1]));
                pl[ri][2] = fmaf(gl0, w0.z, fmaf(gl1, w1.z, pl[ri][2]));
                pl[ri][3] = fmaf(gl0, w0.w, fmaf(gl1, w1.w, pl[ri][3]));
            }
    }
    // reduce over the 4 lanes of each quad
    #pragma unroll
    for (int o = 1; o <= 2; o <<= 1)
        #pragma unroll
        for (int ri = 0; ri < 4; ri++)
            #pragma unroll
            for (int h = 0; h < 4; h++)
                pl[ri][h] += __shfl_xor_sync(0xffffffffu, pl[ri][h], o);

    if (tg == 0){
        #pragma unroll
        for (int mt = 0; mt < 2; mt++)
            #pragma unroll
            for (int hi = 0; hi < 2; hi++){
                int rrow = wm*32 + mt*16 + g + 8*hi;
                #pragma unroll
                for (int h = 0; h < 4; h++)
                    atomicAdd(&Lsm[rrow*4 + h], pl[mt*2+hi][h]);
            }
    }
    __syncthreads();

    // ---- Fused tail: softmax over K + r/u reductions (warps 0..3) ----
    if (wid < 4){
        int s_mb = Flg[0];
        size_t T = (size_t)blockIdx.x*4 + wid;
        size_t row = T*32 + lane;

        float4 l4 = *(const float4*)&Lsm[(wid*32 + lane)*4];
        float l[4] = {l4.x, l4.y, l4.z, l4.w};

        bool m;
        if (s_mb) m = ((const unsigned char*)mask)[row] != 0;
        else      m = ((const unsigned int*)mask)[row] != 0u;

        float a[4];
        #pragma unroll
        for (int h = 0; h < 4; h++){
            float v = m ? l[h] : -3.402823466e38f;
            float mx = wmax(v);
            float e  = m ? __expf(l[h] - mx) : 0.f;
            float sden = wsum(e);
            a[h] = (sden > 0.f) ? (e / sden) : 0.f;
        }

        float* alpha_out = out + 2 * (NTOK * 12);
        ((float4*)alpha_out)[row] = make_float4(a[0], a[1], a[2], a[3]);

        float rr[3], uu[3];
        #pragma unroll
        for (int d = 0; d < 3; d++){
            rr[d] = r[row*3 + d];
            uu[d] = u[row*3 + d];
        }

        float orv = 0.f, ouv = 0.f;
        #pragma unroll
        for (int p = 0; p < 12; p++){
            float v1 = a[p/3] * rr[p%3];
            float v2 = a[p/3] * uu[p%3];
            #pragma unroll
            for (int o = 16; o; o >>= 1){
                v1 += __shfl_xor_sync(0xffffffffu, v1, o);
                v2 += __shfl_xor_sync(0xffffffffu, v2, o);
            }
            if (lane == p) orv = v1;
            if (lane == p) ouv = v2;
        }
        if (lane < 12){
            out[T*12 + lane]           = orv;   // v_r
            out[NTOK*12 + T*12 + lane] = ouv;   // v_u
        }
    }
}

// ---------------------------------------------------------------------------
extern "C" void kernel_launch(void* const* d_in, const int* in_sizes, int n_in,
                              void* d_out, int out_size){
    (void)in_sizes; (void)n_in; (void)out_size;
    const float* inv  = (const float*)d_in[0];   // inv_tok (B,N,K,D)
    const float* ego  = (const float*)d_in[1];   // ego_ctx (B,N,256)
    const float* r    = (const float*)d_in[2];   // (B,N,K,3)
    const float* u    = (const float*)d_in[3];   // (B,N,K,3)
    const void*  mask = d_in[4];                 // (B,N,K) bool/int
    const float* We   = (const float*)d_in[5];   // W_ego (256,256)
    const float* be   = (const float*)d_in[6];   // b_ego (256)
    const float* lns  = (const float*)d_in[7];   // ln_scale (256)
    const float* lnb  = (const float*)d_in[8];   // ln_bias (256)
    const float* Wh   = (const float*)d_in[9];   // W_h (512,256)
    const float* bh   = (const float*)d_in[10];  // b_h (256)
    const float* Wl   = (const float*)d_in[11];  // W_logit (256,4)
    // d_in[12] = b_logit: softmax-invariant, unused.

    cudaFuncSetAttribute(k_main,   cudaFuncAttributeMaxDynamicSharedMemorySize, MAIN_SMEM);
    cudaFuncSetAttribute(k_egomma, cudaFuncAttributeMaxDynamicSharedMemorySize, EGO_SMEM);

    k_prep<<<272, 256>>>(Wh, We, be, mask);
    k_egomma<<<NTOK/128, 512, EGO_SMEM>>>(ego, bh);
    k_nop<<<1, 32>>>();
    k_main<<<2048, 1024, MAIN_SMEM>>>(inv, lns, lnb, Wl, r, u, mask, (float*)d_out);
}